// round 3
// baseline (speedup 1.0000x reference)
#include <cuda_runtime.h>
#include <cuda_bf16.h>

// out[i] = sin(in[i,0]) * sin(in[i,1]); N = 16777216 rows.
// Pure streaming: 16 outputs/thread, __ldcs/__stcs (evict-first) since
// data has zero reuse. 8x LDG.128 batched up front (MLP_p1=8), 4x STG.128.

__global__ __launch_bounds__(256) void sin_prod_kernel(
    const float4* __restrict__ in,   // pairs: .x=a,.y=b,.z=a',.w=b'
    float4* __restrict__ out,
    int n16)                         // number of 16-row groups = N/16
{
    int i = blockIdx.x * blockDim.x + threadIdx.x;
    if (i >= n16) return;

    const float4* pin = in + 8 * (size_t)i;

    // batch all 8 loads up front -> 8 outstanding LDG.128 per thread
    float4 p0 = __ldcs(pin + 0);
    float4 p1 = __ldcs(pin + 1);
    float4 p2 = __ldcs(pin + 2);
    float4 p3 = __ldcs(pin + 3);
    float4 p4 = __ldcs(pin + 4);
    float4 p5 = __ldcs(pin + 5);
    float4 p6 = __ldcs(pin + 6);
    float4 p7 = __ldcs(pin + 7);

    float4 r0, r1, r2, r3;
    r0.x = __sinf(p0.x) * __sinf(p0.y);
    r0.y = __sinf(p0.z) * __sinf(p0.w);
    r0.z = __sinf(p1.x) * __sinf(p1.y);
    r0.w = __sinf(p1.z) * __sinf(p1.w);
    r1.x = __sinf(p2.x) * __sinf(p2.y);
    r1.y = __sinf(p2.z) * __sinf(p2.w);
    r1.z = __sinf(p3.x) * __sinf(p3.y);
    r1.w = __sinf(p3.z) * __sinf(p3.w);
    r2.x = __sinf(p4.x) * __sinf(p4.y);
    r2.y = __sinf(p4.z) * __sinf(p4.w);
    r2.z = __sinf(p5.x) * __sinf(p5.y);
    r2.w = __sinf(p5.z) * __sinf(p5.w);
    r3.x = __sinf(p6.x) * __sinf(p6.y);
    r3.y = __sinf(p6.z) * __sinf(p6.w);
    r3.z = __sinf(p7.x) * __sinf(p7.y);
    r3.w = __sinf(p7.z) * __sinf(p7.w);

    float4* pout = out + 4 * (size_t)i;
    __stcs(pout + 0, r0);
    __stcs(pout + 1, r1);
    __stcs(pout + 2, r2);
    __stcs(pout + 3, r3);
}

extern "C" void kernel_launch(void* const* d_in, const int* in_sizes, int n_in,
                              void* d_out, int out_size)
{
    const float* in = (const float*)d_in[0];
    float* out = (float*)d_out;

    int n = out_size;           // rows (16777216), divisible by 16
    int n16 = n / 16;           // 1048576 groups

    int threads = 256;
    int blocks = (n16 + threads - 1) / threads;   // 4096
    sin_prod_kernel<<<blocks, threads>>>(
        (const float4*)in, (float4*)out, n16);
}

// round 4
// speedup vs baseline: 1.3080x; 1.3080x over previous
#include <cuda_runtime.h>
#include <cuda_bf16.h>

// out[i] = sin(in[i,0]) * sin(in[i,1]); N = 16777216 rows.
// R2 geometry (known good: 27.7us): 8 outputs/thread, 4x LDG.128 batched,
// 2x STG.128. Single change vs R2: stores use .cs (evict-first) to keep the
// zero-reuse output stream from displacing input lines in L2.

__global__ __launch_bounds__(256) void sin_prod_kernel(
    const float4* __restrict__ in,   // pairs: .x=a,.y=b,.z=a',.w=b'
    float4* __restrict__ out,
    int n8)                          // number of 8-row groups = N/8
{
    int i = blockIdx.x * blockDim.x + threadIdx.x;
    if (i >= n8) return;

    // 4 outstanding LDG.128 per thread (MLP_p1=4 — sweet spot from R2/R3)
    float4 p0 = in[4 * i + 0];
    float4 p1 = in[4 * i + 1];
    float4 p2 = in[4 * i + 2];
    float4 p3 = in[4 * i + 3];

    float4 r0, r1;
    r0.x = __sinf(p0.x) * __sinf(p0.y);
    r0.y = __sinf(p0.z) * __sinf(p0.w);
    r0.z = __sinf(p1.x) * __sinf(p1.y);
    r0.w = __sinf(p1.z) * __sinf(p1.w);
    r1.x = __sinf(p2.x) * __sinf(p2.y);
    r1.y = __sinf(p2.z) * __sinf(p2.w);
    r1.z = __sinf(p3.x) * __sinf(p3.y);
    r1.w = __sinf(p3.z) * __sinf(p3.w);

    __stcs(out + 2 * i + 0, r0);
    __stcs(out + 2 * i + 1, r1);
}

extern "C" void kernel_launch(void* const* d_in, const int* in_sizes, int n_in,
                              void* d_out, int out_size)
{
    const float* in = (const float*)d_in[0];
    float* out = (float*)d_out;

    int n = out_size;          // rows (16777216), divisible by 8
    int n8 = n / 8;            // 2097152 groups

    int threads = 256;
    int blocks = (n8 + threads - 1) / threads;   // 8192
    sin_prod_kernel<<<blocks, threads>>>(
        (const float4*)in, (float4*)out, n8);
}